// round 2
// baseline (speedup 1.0000x reference)
#include <cuda_runtime.h>
#include <math.h>

// GCN: 4 layers over fixed graph. N=100000, E=3200000, hidden=32.
// Plan per launch:
//   1) deg (with self loops), dinv = rsqrt(deg)
//   2) CSR by dst via counting sort (block scan for offsets, atomic placement)
//   3) per layer: g[v] = dinv[v]*(h[v]@W); out[u] = act(dinv[u]*sum_{s in N(u)} g[s] + b)
// All feature gathers hit L2 (12.8MB working set). No float atomics anywhere.

#define N_MAX 100000
#define E_MAX 3200000
#define TOT_MAX (N_MAX + E_MAX)
#define FULLMASK 0xffffffffu

__device__ int   g_deg[N_MAX];
__device__ int   g_off[N_MAX + 1];
__device__ int   g_cur[N_MAX];
__device__ int   g_csr[TOT_MAX];
__device__ float g_dinv[N_MAX];
__device__ float g_A[N_MAX * 32];   // "g" buffer (pre-scaled transformed features)
__device__ float g_B[N_MAX * 32];   // "h" buffer (post-aggregation activations)
__device__ float g_s[N_MAX];        // width-1 buffer for final layer
__device__ int   g_bsums[512];

// ---------------- graph build ----------------

__global__ void k_init(int n) {
    int i = blockIdx.x * blockDim.x + threadIdx.x;
    if (i < n) { g_deg[i] = 1; g_cur[i] = 0; }   // deg starts at 1 (self loop)
}

__global__ void k_count(const int* __restrict__ ei, int E) {
    int i = blockIdx.x * blockDim.x + threadIdx.x;
    if (i < E) atomicAdd(&g_deg[ei[E + i]], 1);  // dst row of edge_index
}

__global__ void k_dinv(int n) {
    int i = blockIdx.x * blockDim.x + threadIdx.x;
    if (i < n) g_dinv[i] = rsqrtf((float)g_deg[i]);  // deg >= 1 always
}

// Block-wise exclusive scan of g_deg into g_off (3 phases).
__global__ void k_scanA(int n) {
    __shared__ int sh[512];
    int t = threadIdx.x;
    int i = blockIdx.x * 512 + t;
    int v = (i < n) ? g_deg[i] : 0;
    sh[t] = v;
    __syncthreads();
    #pragma unroll
    for (int d = 1; d < 512; d <<= 1) {
        int x = (t >= d) ? sh[t - d] : 0;
        __syncthreads();
        sh[t] += x;
        __syncthreads();
    }
    if (i < n) g_off[i] = sh[t] - v;           // exclusive within block
    if (t == 511) g_bsums[blockIdx.x] = sh[511];
}

__global__ void k_scanB(int nb) {
    __shared__ int sh[512];
    int t = threadIdx.x;
    int v = (t < nb) ? g_bsums[t] : 0;
    sh[t] = v;
    __syncthreads();
    #pragma unroll
    for (int d = 1; d < 512; d <<= 1) {
        int x = (t >= d) ? sh[t - d] : 0;
        __syncthreads();
        sh[t] += x;
        __syncthreads();
    }
    if (t < nb) g_bsums[t] = sh[t] - v;        // exclusive block prefix
}

__global__ void k_scanC(int n, int total) {
    int i = blockIdx.x * 512 + threadIdx.x;
    if (i < n) g_off[i] += g_bsums[blockIdx.x];
    if (blockIdx.x == 0 && threadIdx.x == 0) g_off[n] = total;
}

__global__ void k_fill(const int* __restrict__ ei, int n, int E) {
    int t = blockIdx.x * blockDim.x + threadIdx.x;
    if (t >= n + E) return;
    int s, d;
    if (t < E) { s = ei[t]; d = ei[E + t]; }
    else       { s = t - E; d = s; }           // self loop
    int p = atomicAdd(&g_cur[d], 1);
    g_csr[g_off[d] + p] = s;
}

// ---------------- layers ----------------

// Layer 1 transform: h is (n,1) = x, so g[v][j] = dinv[v]*x[v]*W_in[j]
__global__ void k_l1(const float* __restrict__ x, const float* __restrict__ Win, int n) {
    int t = blockIdx.x * blockDim.x + threadIdx.x;
    if (t >= n * 32) return;
    int v = t >> 5, j = t & 31;
    g_A[t] = x[v] * g_dinv[v] * Win[j];
}

// 32x32 transform: warp per node, lane = output feature. out = dinv[v]*(in[v]@W)
__global__ void k_mid_transform(const float* __restrict__ W,
                                const float* __restrict__ in,
                                float* __restrict__ out, int n) {
    __shared__ float Wsh[1024];
    int t = threadIdx.x;
    for (int i = t; i < 1024; i += blockDim.x) Wsh[i] = W[i];
    __syncthreads();
    int gt = blockIdx.x * blockDim.x + t;
    int v = gt >> 5, lane = gt & 31;
    if (v >= n) return;
    float hv = in[v * 32 + lane];
    float acc = 0.f;
    #pragma unroll
    for (int k = 0; k < 32; k++)
        acc = fmaf(__shfl_sync(FULLMASK, hv, k), Wsh[k * 32 + lane], acc);
    out[v * 32 + lane] = g_dinv[v] * acc;
}

// Aggregation (width 32): warp per node, lane = feature. Coalesced 128B gathers.
__global__ void k_agg32(const float* __restrict__ gin,
                        const float* __restrict__ b,
                        float* __restrict__ hout, int n) {
    int gt = blockIdx.x * blockDim.x + threadIdx.x;
    int u = gt >> 5, lane = gt & 31;
    if (u >= n) return;
    int s0 = g_off[u], s1 = g_off[u + 1];
    float acc = 0.f;
    for (int e0 = s0; e0 < s1; e0 += 32) {
        int idx = (e0 + lane < s1) ? g_csr[e0 + lane] : 0;
        int cnt = min(32, s1 - e0);
        for (int k = 0; k < cnt; k++) {
            int s = __shfl_sync(FULLMASK, idx, k);
            acc += gin[s * 32 + lane];
        }
    }
    float v = g_dinv[u] * acc + b[lane];
    hout[u * 32 + lane] = fmaxf(v, 0.f);
}

// Final transform: g_s[v] = dinv[v]*(h[v]@W_out), warp-reduce over features
__global__ void k_out_transform(const float* __restrict__ Wout,
                                const float* __restrict__ in, int n) {
    int gt = blockIdx.x * blockDim.x + threadIdx.x;
    int v = gt >> 5, lane = gt & 31;
    if (v >= n) return;
    float val = in[v * 32 + lane] * Wout[lane];
    #pragma unroll
    for (int o = 16; o; o >>= 1) val += __shfl_xor_sync(FULLMASK, val, o);
    if (lane == 0) g_s[v] = g_dinv[v] * val;
}

// Final aggregation (width 1) + bias + sigmoid
__global__ void k_agg_out(const float* __restrict__ bout,
                          float* __restrict__ out, int n) {
    int gt = blockIdx.x * blockDim.x + threadIdx.x;
    int u = gt >> 5, lane = gt & 31;
    if (u >= n) return;
    int s0 = g_off[u], s1 = g_off[u + 1];
    float acc = 0.f;
    for (int e = s0 + lane; e < s1; e += 32) acc += g_s[g_csr[e]];
    #pragma unroll
    for (int o = 16; o; o >>= 1) acc += __shfl_xor_sync(FULLMASK, acc, o);
    if (lane == 0) {
        float v = g_dinv[u] * acc + bout[0];
        out[u] = 1.f / (1.f + expf(-v));
    }
}

// ---------------- launch ----------------

extern "C" void kernel_launch(void* const* d_in, const int* in_sizes, int n_in,
                              void* d_out, int out_size) {
    const float* x    = (const float*)d_in[0];
    const int*   ei   = (const int*)  d_in[1];
    const float* Win  = (const float*)d_in[2];
    const float* bin  = (const float*)d_in[3];
    const float* Wmid = (const float*)d_in[4];
    const float* bmid = (const float*)d_in[5];
    const float* Wout = (const float*)d_in[6];
    const float* bout = (const float*)d_in[7];
    float* out = (float*)d_out;

    int n = in_sizes[0];
    int E = in_sizes[1] / 2;
    if (n > N_MAX) n = N_MAX;
    if (E > E_MAX) E = E_MAX;

    void *pA = nullptr, *pB = nullptr;
    cudaGetSymbolAddress(&pA, g_A);
    cudaGetSymbolAddress(&pB, g_B);
    float* A = (float*)pA;
    float* B = (float*)pB;

    const int T = 256;
    int gn   = (n + T - 1) / T;
    int gE   = (E + T - 1) / T;
    int gnE  = (n + E + T - 1) / T;
    int gw   = (n * 32 + T - 1) / T;   // warp-per-node grids
    int nbScan = (n + 511) / 512;
    int total = n + E;

    k_init <<<gn, T>>>(n);
    k_count<<<gE, T>>>(ei, E);
    k_dinv <<<gn, T>>>(n);
    k_scanA<<<nbScan, 512>>>(n);
    k_scanB<<<1, 512>>>(nbScan);
    k_scanC<<<nbScan, 512>>>(n, total);
    k_fill <<<gnE, T>>>(ei, n, E);

    // Layer 1: x -> A(transform) -> B(aggregate+relu)
    k_l1   <<<gw, T>>>(x, Win, n);
    k_agg32<<<gw, T>>>(A, bin, B, n);
    // Layer 2: B -> A -> B
    k_mid_transform<<<gw, T>>>(Wmid, B, A, n);
    k_agg32<<<gw, T>>>(A, bmid, B, n);
    // Layer 3: B -> A -> B
    k_mid_transform<<<gw, T>>>(Wmid, B, A, n);
    k_agg32<<<gw, T>>>(A, bmid, B, n);
    // Layer 4: B -> g_s -> out (sigmoid)
    k_out_transform<<<gw, T>>>(Wout, B, n);
    k_agg_out<<<gw, T>>>(bout, out, n);
}

// round 3
// speedup vs baseline: 1.1204x; 1.1204x over previous
#include <cuda_runtime.h>
#include <math.h>

// GCN 4 layers, N=100000, E=3200000, hidden=32.
// R2: transforms fused into aggregation epilogues; self-loops handled
// in-register (CSR holds only real edges); dinv fused into scan; memset init.

#define N_MAX 100000
#define E_MAX 3200000
#define FULLMASK 0xffffffffu

__device__ int   g_deg[N_MAX];       // in-degree histogram (no self loop)
__device__ int   g_off[N_MAX + 1];
__device__ int   g_cur[N_MAX];
__device__ int   g_csr[E_MAX];
__device__ float g_dinv[N_MAX];
__device__ float g_A[N_MAX * 32];    // g buffers (pre-scaled transformed feats)
__device__ float g_B[N_MAX * 32];
__device__ float g_s[N_MAX];         // width-1 buffer for final layer
__device__ int   g_bsums[512];

// ---------------- graph build ----------------

__global__ void k_count(const int* __restrict__ ei, int E) {
    int i = blockIdx.x * blockDim.x + threadIdx.x;
    if (i < E) atomicAdd(&g_deg[ei[E + i]], 1);
}

// Block scan of g_deg -> g_off (exclusive within block); also dinv = rsqrt(deg+1).
__global__ void k_scanA(int n) {
    __shared__ int sh[512];
    int t = threadIdx.x;
    int i = blockIdx.x * 512 + t;
    int v = (i < n) ? g_deg[i] : 0;
    if (i < n) g_dinv[i] = rsqrtf((float)(v + 1));
    sh[t] = v;
    __syncthreads();
    #pragma unroll
    for (int d = 1; d < 512; d <<= 1) {
        int x = (t >= d) ? sh[t - d] : 0;
        __syncthreads();
        sh[t] += x;
        __syncthreads();
    }
    if (i < n) g_off[i] = sh[t] - v;
    if (t == 511) g_bsums[blockIdx.x] = sh[511];
}

__global__ void k_scanB(int nb) {
    __shared__ int sh[512];
    int t = threadIdx.x;
    int v = (t < nb) ? g_bsums[t] : 0;
    sh[t] = v;
    __syncthreads();
    #pragma unroll
    for (int d = 1; d < 512; d <<= 1) {
        int x = (t >= d) ? sh[t - d] : 0;
        __syncthreads();
        sh[t] += x;
        __syncthreads();
    }
    if (t < nb) g_bsums[t] = sh[t] - v;
}

__global__ void k_scanC(int n, int E) {
    int i = blockIdx.x * 512 + threadIdx.x;
    if (i < n) g_off[i] += g_bsums[blockIdx.x];
    if (blockIdx.x == 0 && threadIdx.x == 0) g_off[n] = E;
}

__global__ void k_fill(const int* __restrict__ ei, int E) {
    int t = blockIdx.x * blockDim.x + threadIdx.x;
    if (t >= E) return;
    int s = ei[t];
    int d = ei[E + t];
    int p = atomicAdd(&g_cur[d], 1);
    g_csr[g_off[d] + p] = s;
}

// ---------------- layers ----------------

// Layer 1 transform: g1[v][j] = dinv[v]*x[v]*W_in[j]
__global__ void k_l1(const float* __restrict__ x, const float* __restrict__ Win, int n) {
    int t = blockIdx.x * blockDim.x + threadIdx.x;
    if (t >= n * 32) return;
    int v = t >> 5, j = t & 31;
    g_A[t] = x[v] * g_dinv[v] * Win[j];
}

// Warp-level neighbor gather: sum of gin rows over CSR range + self row.
__device__ __forceinline__ float gather_row(const float* __restrict__ gin,
                                            int u, int lane) {
    int s0 = g_off[u], s1 = g_off[u + 1];
    float a0 = gin[u * 32 + lane];   // self loop contribution
    float a1 = 0.f, a2 = 0.f, a3 = 0.f;
    int e = s0;
    for (; e + 32 <= s1; e += 32) {
        int idx = g_csr[e + lane];
        #pragma unroll
        for (int k = 0; k < 32; k += 4) {
            int i0 = __shfl_sync(FULLMASK, idx, k);
            int i1 = __shfl_sync(FULLMASK, idx, k + 1);
            int i2 = __shfl_sync(FULLMASK, idx, k + 2);
            int i3 = __shfl_sync(FULLMASK, idx, k + 3);
            a0 += gin[i0 * 32 + lane];
            a1 += gin[i1 * 32 + lane];
            a2 += gin[i2 * 32 + lane];
            a3 += gin[i3 * 32 + lane];
        }
    }
    int rem = s1 - e;
    if (rem > 0) {
        int idx = (lane < rem) ? g_csr[e + lane] : 0;
        for (int k = 0; k < rem; k++) {
            int s = __shfl_sync(FULLMASK, idx, k);
            a0 += gin[s * 32 + lane];
        }
    }
    return (a0 + a1) + (a2 + a3);
}

// Aggregate + relu + fused 32x32 transform -> next g buffer.
__global__ void k_agg_mid(const float* __restrict__ gin,
                          const float* __restrict__ b,
                          const float* __restrict__ W,
                          float* __restrict__ gout, int n) {
    __shared__ float Wsh[1024];
    int t = threadIdx.x;
    for (int i = t; i < 1024; i += blockDim.x) Wsh[i] = W[i];
    __syncthreads();
    int gt = blockIdx.x * blockDim.x + t;
    int u = gt >> 5, lane = gt & 31;
    if (u >= n) return;
    float dinv = g_dinv[u];
    float acc = gather_row(gin, u, lane);
    float h = fmaxf(fmaf(dinv, acc, b[lane]), 0.f);
    float acc2 = 0.f;
    #pragma unroll
    for (int k = 0; k < 32; k++)
        acc2 = fmaf(__shfl_sync(FULLMASK, h, k), Wsh[k * 32 + lane], acc2);
    gout[u * 32 + lane] = dinv * acc2;
}

// Aggregate + relu + fused scalar output transform -> g_s.
__global__ void k_agg_last(const float* __restrict__ gin,
                           const float* __restrict__ b,
                           const float* __restrict__ Wout, int n) {
    int gt = blockIdx.x * blockDim.x + threadIdx.x;
    int u = gt >> 5, lane = gt & 31;
    if (u >= n) return;
    float dinv = g_dinv[u];
    float acc = gather_row(gin, u, lane);
    float h = fmaxf(fmaf(dinv, acc, b[lane]), 0.f);
    float val = h * Wout[lane];
    #pragma unroll
    for (int o = 16; o; o >>= 1) val += __shfl_xor_sync(FULLMASK, val, o);
    if (lane == 0) g_s[u] = dinv * val;
}

// Final width-1 aggregation + bias + sigmoid.
__global__ void k_agg_out(const float* __restrict__ bout,
                          float* __restrict__ out, int n) {
    int gt = blockIdx.x * blockDim.x + threadIdx.x;
    int u = gt >> 5, lane = gt & 31;
    if (u >= n) return;
    int s0 = g_off[u], s1 = g_off[u + 1];
    float acc = 0.f;
    for (int e = s0 + lane; e < s1; e += 32) acc += g_s[g_csr[e]];
    #pragma unroll
    for (int o = 16; o; o >>= 1) acc += __shfl_xor_sync(FULLMASK, acc, o);
    if (lane == 0) {
        float v = fmaf(g_dinv[u], acc + g_s[u], bout[0]);
        out[u] = 1.f / (1.f + expf(-v));
    }
}

// ---------------- launch ----------------

extern "C" void kernel_launch(void* const* d_in, const int* in_sizes, int n_in,
                              void* d_out, int out_size) {
    const float* x    = (const float*)d_in[0];
    const int*   ei   = (const int*)  d_in[1];
    const float* Win  = (const float*)d_in[2];
    const float* bin  = (const float*)d_in[3];
    const float* Wmid = (const float*)d_in[4];
    const float* bmid = (const float*)d_in[5];
    const float* Wout = (const float*)d_in[6];
    const float* bout = (const float*)d_in[7];
    float* out = (float*)d_out;

    int n = in_sizes[0];
    int E = in_sizes[1] / 2;
    if (n > N_MAX) n = N_MAX;
    if (E > E_MAX) E = E_MAX;

    void *pA = nullptr, *pB = nullptr, *pDeg = nullptr, *pCur = nullptr;
    cudaGetSymbolAddress(&pA, g_A);
    cudaGetSymbolAddress(&pB, g_B);
    cudaGetSymbolAddress(&pDeg, g_deg);
    cudaGetSymbolAddress(&pCur, g_cur);
    float* A = (float*)pA;
    float* B = (float*)pB;

    const int T = 256;
    int gE   = (E + T - 1) / T;
    int gw   = (n * 32 + T - 1) / T;     // warp-per-node grids
    int nbScan = (n + 511) / 512;

    cudaMemsetAsync(pDeg, 0, n * sizeof(int), 0);
    cudaMemsetAsync(pCur, 0, n * sizeof(int), 0);

    k_count<<<gE, T>>>(ei, E);
    k_scanA<<<nbScan, 512>>>(n);
    k_scanB<<<1, 512>>>(nbScan);
    k_scanC<<<nbScan, 512>>>(n, E);
    k_fill <<<gE, T>>>(ei, E);

    k_l1      <<<gw, T>>>(x, Win, n);
    k_agg_mid <<<gw, T>>>(A, bin,  Wmid, B, n);   // layer 1 agg + layer 2 transform
    k_agg_mid <<<gw, T>>>(B, bmid, Wmid, A, n);   // layer 2 agg + layer 3 transform
    k_agg_last<<<gw, T>>>(A, bmid, Wout, n);      // layer 3 agg + layer 4 transform
    k_agg_out <<<gw, T>>>(bout, out, n);          // layer 4 agg + sigmoid
}